// round 2
// baseline (speedup 1.0000x reference)
#include <cuda_runtime.h>
#include <math.h>

#define T_ 30
#define C_ 512
#define N_ 784
#define K_ 64
#define KD_ (K_ * C_)   // 32768

// ---------------- device scratch (no allocs allowed) ----------------
__device__ float g_wT[C_ * K_];            // conv_w transposed: [c][k]
__device__ float g_aT[T_ * N_ * K_];       // a' = softmax * invn, layout [t][n][k]  (~6 MB)
__device__ float g_asum[T_ * K_];          // sum_n a[t,k,n]
__device__ float g_vlad[T_ * K_ * C_];     // [t][k][c]  (~4 MB)
__device__ float g_gss[T_];                // global sumsq per t

// ---------------- pass 0: transpose W, zero accumulators ----------------
__global__ void prep_kernel(const float* __restrict__ w) {
    int i = blockIdx.x * 256 + threadIdx.x;
    if (i < C_ * K_) {
        int k = i / C_, c = i % C_;
        g_wT[c * K_ + k] = w[i];
    }
    if (i < T_ * K_) g_asum[i] = 0.f;
    if (i < T_)      g_gss[i]  = 0.f;
}

// ---------------- pass 1: invnorm + logits GEMM + softmax -> aT', asum ----------------
// grid: (ceil(N/64)=13, T), block 256
__global__ __launch_bounds__(256) void assign_kernel(
    const float* __restrict__ x, const float* __restrict__ bias)
{
    const int t   = blockIdx.y;
    const int n0  = blockIdx.x * 64;
    const int tid = threadIdx.x;
    const int ty  = tid >> 4;   // 0..15 -> k = ty*4..+3
    const int tx  = tid & 15;   // 0..15 -> n = tx*4..+3

    __shared__ float Ws[32 * 64];     // wT chunk [ci][k]
    __shared__ float Xs[32 * 64];     // x  chunk [ci][nj]
    __shared__ float Ls[64 * 64];     // logits [k][n]
    __shared__ float red[4 * 64];
    __shared__ float invn_s[64];
    __shared__ float bsm[64];
    __shared__ float rinvs[64];

    if (tid < 64) bsm[tid] = bias[tid];

    float acc[4][4];
#pragma unroll
    for (int i = 0; i < 4; i++)
#pragma unroll
        for (int j = 0; j < 4; j++) acc[i][j] = 0.f;
    float ss = 0.f;

    const float* xt = x + (size_t)t * C_ * N_;

    for (int cc = 0; cc < 16; cc++) {
#pragma unroll
        for (int j = 0; j < 8; j++) {
            int e = tid + j * 256;
            Ws[e] = g_wT[cc * 2048 + e];
        }
#pragma unroll
        for (int j = 0; j < 8; j++) {
            int e  = tid + j * 256;
            int ci = e >> 6, nj = e & 63;
            int n  = n0 + nj;
            Xs[e] = (n < N_) ? xt[(size_t)(cc * 32 + ci) * N_ + n] : 0.f;
        }
        __syncthreads();

        if (tid < 64) {  // per-column sumsq accumulation (for invn)
#pragma unroll
            for (int ci = 0; ci < 32; ci++) {
                float v = Xs[ci * 64 + tid];
                ss += v * v;
            }
        }
#pragma unroll
        for (int ci = 0; ci < 32; ci++) {
            float4 wv = *(const float4*)&Ws[ci * 64 + ty * 4];
            float4 xv = *(const float4*)&Xs[ci * 64 + tx * 4];
            acc[0][0] += wv.x * xv.x; acc[0][1] += wv.x * xv.y; acc[0][2] += wv.x * xv.z; acc[0][3] += wv.x * xv.w;
            acc[1][0] += wv.y * xv.x; acc[1][1] += wv.y * xv.y; acc[1][2] += wv.y * xv.z; acc[1][3] += wv.y * xv.w;
            acc[2][0] += wv.z * xv.x; acc[2][1] += wv.z * xv.y; acc[2][2] += wv.z * xv.z; acc[2][3] += wv.z * xv.w;
            acc[3][0] += wv.w * xv.x; acc[3][1] += wv.w * xv.y; acc[3][2] += wv.w * xv.z; acc[3][3] += wv.w * xv.w;
        }
        __syncthreads();
    }

    if (tid < 64) {
        invn_s[tid] = 1.f / fmaxf(sqrtf(ss), 1e-12f);
    }
    __syncthreads();

    // logits = acc * invn[n] + b[k] -> Ls
#pragma unroll
    for (int i = 0; i < 4; i++) {
        int k = ty * 4 + i;
        float b = bsm[k];
#pragma unroll
        for (int j = 0; j < 4; j++) {
            int n = tx * 4 + j;
            Ls[k * 64 + n] = acc[i][j] * invn_s[n] + b;
        }
    }
    __syncthreads();

    // softmax over k (64) per column; 4 threads per column, 16 rows each
    const int col = tid & 63, part = tid >> 6;
    float m = -1e30f;
#pragma unroll
    for (int kk = 0; kk < 16; kk++) m = fmaxf(m, Ls[(part * 16 + kk) * 64 + col]);
    red[part * 64 + col] = m;
    __syncthreads();
    m = fmaxf(fmaxf(red[col], red[64 + col]), fmaxf(red[128 + col], red[192 + col]));
    __syncthreads();
    float s = 0.f;
#pragma unroll
    for (int kk = 0; kk < 16; kk++) {
        float e = __expf(Ls[(part * 16 + kk) * 64 + col] - m);
        Ls[(part * 16 + kk) * 64 + col] = e;
        s += e;
    }
    red[part * 64 + col] = s;
    __syncthreads();
    float S    = red[col] + red[64 + col] + red[128 + col] + red[192 + col];
    float rinv = 1.f / S;
    if (part == 0) rinvs[col] = rinv;
    __syncthreads();

    // write aT' = a * invn  (layout [t][n][k])
    const int n = n0 + col;
    if (n < N_) {
        float  sc  = rinv * invn_s[col];
        float* dst = &g_aT[((size_t)t * N_ + n) * K_ + part * 16];
#pragma unroll
        for (int kk = 0; kk < 16; kk++)
            dst[kk] = Ls[(part * 16 + kk) * 64 + col] * sc;
    }

    // partial asum per k over this block's valid columns
    const int ncols = min(64, N_ - n0);
    if (tid < 64) {
        float as = 0.f;
        for (int c2 = 0; c2 < ncols; c2++)
            as += Ls[tid * 64 + c2] * rinvs[c2];
        atomicAdd(&g_asum[t * K_ + tid], as);
    }
}

// ---------------- pass 2: VLAD GEMM: vlad[k][c] = sum_n a'[n][k]*x[c][n] - asum[k]*cent[k][c] ----------------
// grid: (C/64=8, T), block 256
__global__ __launch_bounds__(256) void vlad_kernel(
    const float* __restrict__ x, const float* __restrict__ cent)
{
    const int t   = blockIdx.y;
    const int c0  = blockIdx.x * 64;
    const int tid = threadIdx.x;
    const int ty  = tid >> 4;
    const int tx  = tid & 15;

    __shared__ float As[32 * 64];    // [nn][k]
    __shared__ float XsT[32 * 68];   // [nn][ci] (pad 68 keeps float4 align, limits conflicts)
    __shared__ float asums[64];

    if (tid < 64) asums[tid] = g_asum[t * 64 + tid];

    float acc[4][4];
#pragma unroll
    for (int i = 0; i < 4; i++)
#pragma unroll
        for (int j = 0; j < 4; j++) acc[i][j] = 0.f;

    const float* xt  = x + (size_t)t * C_ * N_;
    const float* aTt = g_aT + (size_t)t * N_ * K_;

    for (int nc = 0; nc < 25; nc++) {
        const int n0 = nc * 32;
#pragma unroll
        for (int j = 0; j < 8; j++) {
            int e  = tid + j * 256;
            int nn = e >> 6, k = e & 63;
            As[e] = (n0 + nn < N_) ? aTt[(size_t)(n0 + nn) * K_ + k] : 0.f;
        }
#pragma unroll
        for (int j = 0; j < 8; j++) {
            int e  = tid + j * 256;
            int ci = e >> 5, nn = e & 31;
            float v = (n0 + nn < N_) ? xt[(size_t)(c0 + ci) * N_ + n0 + nn] : 0.f;
            XsT[nn * 68 + ci] = v;
        }
        __syncthreads();
#pragma unroll
        for (int nn = 0; nn < 32; nn++) {
            float4 av = *(const float4*)&As[nn * 64 + ty * 4];
            float4 xv = *(const float4*)&XsT[nn * 68 + tx * 4];
            acc[0][0] += av.x * xv.x; acc[0][1] += av.x * xv.y; acc[0][2] += av.x * xv.z; acc[0][3] += av.x * xv.w;
            acc[1][0] += av.y * xv.x; acc[1][1] += av.y * xv.y; acc[1][2] += av.y * xv.z; acc[1][3] += av.y * xv.w;
            acc[2][0] += av.z * xv.x; acc[2][1] += av.z * xv.y; acc[2][2] += av.z * xv.z; acc[2][3] += av.z * xv.w;
            acc[3][0] += av.w * xv.x; acc[3][1] += av.w * xv.y; acc[3][2] += av.w * xv.z; acc[3][3] += av.w * xv.w;
        }
        __syncthreads();
    }

#pragma unroll
    for (int i = 0; i < 4; i++) {
        int   k  = ty * 4 + i;
        float as = asums[k];
#pragma unroll
        for (int j = 0; j < 4; j++) {
            int c = c0 + tx * 4 + j;
            g_vlad[((size_t)t * K_ + k) * C_ + c] = acc[i][j] - as * cent[k * C_ + c];
        }
    }
}

// ---------------- pass 3: intra-normalization over c per (t,k), accumulate global sumsq ----------------
// grid: (K, T), block 128
__global__ __launch_bounds__(128) void intranorm_kernel() {
    const int t = blockIdx.y, k = blockIdx.x;
    const int tid = threadIdx.x;
    float* v = &g_vlad[((size_t)t * K_ + k) * C_];
    float4 val = ((float4*)v)[tid];
    float ss = val.x * val.x + val.y * val.y + val.z * val.z + val.w * val.w;
#pragma unroll
    for (int o = 16; o; o >>= 1) ss += __shfl_xor_sync(0xffffffff, ss, o);
    __shared__ float wss[4];
    if ((tid & 31) == 0) wss[tid >> 5] = ss;
    __syncthreads();
    float tot = wss[0] + wss[1] + wss[2] + wss[3];
    float sc  = 1.f / fmaxf(sqrtf(tot), 1e-12f);
    val.x *= sc; val.y *= sc; val.z *= sc; val.w *= sc;
    ((float4*)v)[tid] = val;
    if (tid == 0) atomicAdd(&g_gss[t], tot * sc * sc);
}

// ---------------- pass 4: global normalize + sum over t ----------------
// grid: KD/256 = 128, block 256
__global__ __launch_bounds__(256) void finalize_kernel(float* __restrict__ out) {
    __shared__ float gsc[T_];
    const int tid = threadIdx.x;
    if (tid < T_) gsc[tid] = 1.f / fmaxf(sqrtf(g_gss[tid]), 1e-12f);
    __syncthreads();
    const int i = blockIdx.x * 256 + tid;
    float s = 0.f;
    for (int t = 0; t < T_; t++)
        s += g_vlad[(size_t)t * KD_ + i] * gsc[t];
    out[i] = s;
}

// ---------------- launch ----------------
extern "C" void kernel_launch(void* const* d_in, const int* in_sizes, int n_in,
                              void* d_out, int out_size) {
    const float* x1     = (const float*)d_in[0];   // [30,512,28,28]
    const float* cent   = (const float*)d_in[1];   // [64,512]
    const float* conv_w = (const float*)d_in[2];   // [64,512]
    const float* conv_b = (const float*)d_in[3];   // [64]
    float* out = (float*)d_out;                    // [1, 32768]

    prep_kernel<<<128, 256>>>(conv_w);
    {
        dim3 g((N_ + 63) / 64, T_);
        assign_kernel<<<g, 256>>>(x1, conv_b);
    }
    {
        dim3 g(C_ / 64, T_);
        vlad_kernel<<<g, 256>>>(x1, cent);
    }
    {
        dim3 g(K_, T_);
        intranorm_kernel<<<g, 128>>>();
    }
    finalize_kernel<<<KD_ / 256, 256>>>(out);
}

// round 5
// speedup vs baseline: 1.3209x; 1.3209x over previous
#include <cuda_runtime.h>
#include <math.h>

#define T_ 30
#define C_ 512
#define N_ 784
#define K_ 64
#define KD_ (K_ * C_)   // 32768

// ---------------- device scratch (no allocs allowed) ----------------
__device__ float g_wT[C_ * K_];            // conv_w transposed: [c][k]
__device__ float g_aT[T_ * N_ * K_];       // a' = softmax * invn, layout [t][n][k]
__device__ float g_asum[T_ * K_];          // sum_n a[t,k,n]
__device__ float g_vlad[T_ * K_ * C_];     // [t][k][c]
__device__ float g_gss[T_];                // global sumsq per t

// ---------------- packed f32x2 helpers ----------------
typedef unsigned long long u64;
__device__ __forceinline__ u64 pk2(float lo, float hi) {
    u64 r;
    asm("mov.b64 %0, {%1, %2};" : "=l"(r) : "f"(lo), "f"(hi));
    return r;
}
__device__ __forceinline__ void upk2(u64 v, float& lo, float& hi) {
    asm("mov.b64 {%0, %1}, %2;" : "=f"(lo), "=f"(hi) : "l"(v));
}
__device__ __forceinline__ void fma2(u64& d, u64 a, u64 b) {
    asm("fma.rn.f32x2 %0, %1, %2, %0;" : "+l"(d) : "l"(a), "l"(b));
}

// ---------------- pass 0: transpose W, zero accumulators ----------------
__global__ void prep_kernel(const float* __restrict__ w) {
    int i = blockIdx.x * 256 + threadIdx.x;
    if (i < C_ * K_) {
        int k = i / C_, c = i % C_;
        g_wT[c * K_ + k] = w[i];
    }
    if (i < T_ * K_ * C_) g_vlad[i] = 0.f;
    if (i < T_ * K_)      g_asum[i] = 0.f;
    if (i < T_)           g_gss[i]  = 0.f;
}

// ---------------- pass 1: invnorm + logits GEMM + softmax -> aT', asum ----------------
// grid: (13, T), block 128.  Tile: K=64 x N=64, per-thread 8k x 4n via f32x2.
__global__ __launch_bounds__(128) void assign_kernel(
    const float* __restrict__ x, const float* __restrict__ bias)
{
    const int t   = blockIdx.y;
    const int n0  = blockIdx.x * 64;
    const int tid = threadIdx.x;
    const int tyk = tid >> 4;          // 0..7  -> k0 = tyk*8
    const int txn = tid & 15;          // 0..15 -> nl = txn*4
    const int k0  = tyk * 8;
    const int nl  = txn * 4;

    __shared__ float Ws[32 * 64];      // [ci][k]
    __shared__ float Xs[32 * 64];      // [ci][nj]
    __shared__ float Ls[64 * 64];      // logits/exp [k][n]
    __shared__ float red[2 * 64];
    __shared__ float invn_s[64];
    __shared__ float rinvs[64];
    __shared__ float bsm[64];

    if (tid < 64) bsm[tid] = bias[tid];

    u64 acc[4][4];
#pragma unroll
    for (int p = 0; p < 4; p++)
#pragma unroll
        for (int j = 0; j < 4; j++) acc[p][j] = 0ull;

    const int col  = tid & 63;
    const int half = tid >> 6;
    float ss = 0.f;

    const float* xt = x + (size_t)t * C_ * N_;

    for (int cc = 0; cc < 16; cc++) {
#pragma unroll
        for (int j = 0; j < 4; j++) {
            int idx4 = tid + j * 128;
            ((float4*)Ws)[idx4] = ((const float4*)(g_wT + cc * 2048))[idx4];
        }
#pragma unroll
        for (int j = 0; j < 4; j++) {
            int idx4 = tid + j * 128;
            int ci = idx4 >> 4, c4 = idx4 & 15;
            int n  = n0 + c4 * 4;
            float4 v = make_float4(0.f, 0.f, 0.f, 0.f);
            if (n < N_) v = *(const float4*)&xt[(size_t)(cc * 32 + ci) * N_ + n];
            ((float4*)Xs)[idx4] = v;
        }
        __syncthreads();

        // per-column sumsq (2 threads per column, 16 ci each)
#pragma unroll
        for (int ci = half * 16; ci < half * 16 + 16; ci++) {
            float v = Xs[ci * 64 + col];
            ss += v * v;
        }

#pragma unroll
        for (int ci = 0; ci < 32; ci++) {
            float4 wa = *(const float4*)&Ws[ci * 64 + k0];
            float4 wb = *(const float4*)&Ws[ci * 64 + k0 + 4];
            float4 xv = *(const float4*)&Xs[ci * 64 + nl];
            u64 wp0 = pk2(wa.x, wa.y), wp1 = pk2(wa.z, wa.w);
            u64 wp2 = pk2(wb.x, wb.y), wp3 = pk2(wb.z, wb.w);
            u64 xd0 = pk2(xv.x, xv.x), xd1 = pk2(xv.y, xv.y);
            u64 xd2 = pk2(xv.z, xv.z), xd3 = pk2(xv.w, xv.w);
            fma2(acc[0][0], wp0, xd0); fma2(acc[0][1], wp0, xd1);
            fma2(acc[0][2], wp0, xd2); fma2(acc[0][3], wp0, xd3);
            fma2(acc[1][0], wp1, xd0); fma2(acc[1][1], wp1, xd1);
            fma2(acc[1][2], wp1, xd2); fma2(acc[1][3], wp1, xd3);
            fma2(acc[2][0], wp2, xd0); fma2(acc[2][1], wp2, xd1);
            fma2(acc[2][2], wp2, xd2); fma2(acc[2][3], wp2, xd3);
            fma2(acc[3][0], wp3, xd0); fma2(acc[3][1], wp3, xd1);
            fma2(acc[3][2], wp3, xd2); fma2(acc[3][3], wp3, xd3);
        }
        __syncthreads();
    }

    // reduce sumsq halves -> invn
    red[half * 64 + col] = ss;
    __syncthreads();
    if (tid < 64) {
        float sst = red[tid] + red[64 + tid];
        invn_s[tid] = 1.f / fmaxf(sqrtf(sst), 1e-12f);
    }
    __syncthreads();

    // unpack accumulators -> logits in Ls
    // acc[p][j]: lane-lo = (k0+2p, nl+j), lane-hi = (k0+2p+1, nl+j)
#pragma unroll
    for (int p = 0; p < 4; p++) {
        int r0 = k0 + 2 * p, r1 = r0 + 1;
        float b0 = bsm[r0], b1 = bsm[r1];
#pragma unroll
        for (int j = 0; j < 4; j++) {
            int cA = nl + j;
            float iA = invn_s[cA];
            float lo, hi;
            upk2(acc[p][j], lo, hi);
            Ls[r0 * 64 + cA] = lo * iA + b0;
            Ls[r1 * 64 + cA] = hi * iA + b1;
        }
    }
    __syncthreads();

    // softmax over k per column: 2 threads per column, 32 rows each
    float m = -1e30f;
#pragma unroll
    for (int kk = 0; kk < 32; kk++) m = fmaxf(m, Ls[(half * 32 + kk) * 64 + col]);
    red[half * 64 + col] = m;
    __syncthreads();
    m = fmaxf(red[col], red[64 + col]);
    __syncthreads();
    float s = 0.f;
#pragma unroll
    for (int kk = 0; kk < 32; kk++) {
        float e = __expf(Ls[(half * 32 + kk) * 64 + col] - m);
        Ls[(half * 32 + kk) * 64 + col] = e;
        s += e;
    }
    red[half * 64 + col] = s;
    __syncthreads();
    const int  n     = n0 + col;
    const bool valid = (n < N_);
    float S    = red[col] + red[64 + col];
    float rinv = valid ? (1.f / S) : 0.f;
    if (half == 0) rinvs[col] = rinv;
    __syncthreads();

    // write aT' = a * invn  (layout [t][n][k])
    if (valid) {
        float  sc  = rinv * invn_s[col];
        float* dst = &g_aT[((size_t)t * N_ + n) * K_ + half * 32];
#pragma unroll
        for (int kk = 0; kk < 32; kk++)
            dst[kk] = Ls[(half * 32 + kk) * 64 + col] * sc;
    }

    // partial asum per k (staggered columns -> conflict-free)
    if (tid < 64) {
        float as = 0.f;
#pragma unroll 8
        for (int c2 = 0; c2 < 64; c2++) {
            int cix = (c2 + tid) & 63;
            as += Ls[tid * 64 + cix] * rinvs[cix];
        }
        atomicAdd(&g_asum[t * K_ + tid], as);
    }
}

// ---------------- pass 2: VLAD GEMM (split-n x3, atomic accumulate) ----------------
// grid: (8, 3, T), block 128.  Tile: K=64 x C=64, per-thread 8k x 4c via f32x2.
__global__ __launch_bounds__(128) void vlad_kernel(const float* __restrict__ x)
{
    const int t   = blockIdx.z;
    const int c0  = blockIdx.x * 64;
    const int s   = blockIdx.y;
    const int tid = threadIdx.x;
    const int tyk = tid >> 4;
    const int txc = tid & 15;
    const int k0  = tyk * 8;
    const int cl  = txc * 4;

    __shared__ float As[32 * 64];    // [nn][k]
    __shared__ float XsT[32 * 68];   // [nn][ci] padded

    u64 acc[4][4];
#pragma unroll
    for (int p = 0; p < 4; p++)
#pragma unroll
        for (int j = 0; j < 4; j++) acc[p][j] = 0ull;

    const float* xt  = x + (size_t)t * C_ * N_;
    const float* aTt = g_aT + (size_t)t * N_ * K_;

    const int cb = (s == 0) ? 0 : (s == 1 ? 9 : 17);
    const int ce = (s == 0) ? 9 : (s == 1 ? 17 : 25);

    for (int nc = cb; nc < ce; nc++) {
        const int n0 = nc * 32;
#pragma unroll
        for (int j = 0; j < 4; j++) {
            int idx4 = tid + j * 128;
            int nn = idx4 >> 4, k4 = idx4 & 15;
            float4 v = make_float4(0.f, 0.f, 0.f, 0.f);
            if (n0 + nn < N_) v = *(const float4*)&aTt[(size_t)(n0 + nn) * K_ + k4 * 4];
            ((float4*)As)[idx4] = v;
        }
        // FIX (R4): cover full 64-wide c tile: e in [0, 2048), ci in [0,64)
#pragma unroll
        for (int j = 0; j < 16; j++) {
            int e  = tid + j * 128;
            int ci = e >> 5, nn = e & 31;
            float v = (n0 + nn < N_) ? xt[(size_t)(c0 + ci) * N_ + n0 + nn] : 0.f;
            XsT[nn * 68 + ci] = v;
        }
        __syncthreads();
#pragma unroll
        for (int nn = 0; nn < 32; nn++) {
            float4 aa = *(const float4*)&As[nn * 64 + k0];
            float4 ab = *(const float4*)&As[nn * 64 + k0 + 4];
            float4 xv = *(const float4*)&XsT[nn * 68 + cl];
            u64 ap0 = pk2(aa.x, aa.y), ap1 = pk2(aa.z, aa.w);
            u64 ap2 = pk2(ab.x, ab.y), ap3 = pk2(ab.z, ab.w);
            u64 xd0 = pk2(xv.x, xv.x), xd1 = pk2(xv.y, xv.y);
            u64 xd2 = pk2(xv.z, xv.z), xd3 = pk2(xv.w, xv.w);
            fma2(acc[0][0], ap0, xd0); fma2(acc[0][1], ap0, xd1);
            fma2(acc[0][2], ap0, xd2); fma2(acc[0][3], ap0, xd3);
            fma2(acc[1][0], ap1, xd0); fma2(acc[1][1], ap1, xd1);
            fma2(acc[1][2], ap1, xd2); fma2(acc[1][3], ap1, xd3);
            fma2(acc[2][0], ap2, xd0); fma2(acc[2][1], ap2, xd1);
            fma2(acc[2][2], ap2, xd2); fma2(acc[2][3], ap2, xd3);
            fma2(acc[3][0], ap3, xd0); fma2(acc[3][1], ap3, xd1);
            fma2(acc[3][2], ap3, xd2); fma2(acc[3][3], ap3, xd3);
        }
        __syncthreads();
    }

    // epilogue: atomic accumulate partial sums into g_vlad
    // acc[p][j]: lane-lo = (k0+2p, cl+j), lane-hi = (k0+2p+1, cl+j)
#pragma unroll
    for (int p = 0; p < 4; p++) {
        int r0 = k0 + 2 * p, r1 = r0 + 1;
        float* v0 = &g_vlad[((size_t)t * K_ + r0) * C_ + c0 + cl];
        float* v1 = &g_vlad[((size_t)t * K_ + r1) * C_ + c0 + cl];
#pragma unroll
        for (int j = 0; j < 4; j++) {
            float lo, hi;
            upk2(acc[p][j], lo, hi);
            atomicAdd(v0 + j, lo);
            atomicAdd(v1 + j, hi);
        }
    }
}

// ---------------- pass 3: (-asum*cent) + intra-normalization, accumulate global sumsq ----------------
// grid: (K, T), block 128
__global__ __launch_bounds__(128) void intranorm_kernel(const float* __restrict__ cent) {
    const int t = blockIdx.y, k = blockIdx.x;
    const int tid = threadIdx.x;
    float* v = &g_vlad[((size_t)t * K_ + k) * C_];
    float  as = g_asum[t * K_ + k];
    float4 val = ((float4*)v)[tid];
    float4 cw  = ((const float4*)(cent + k * C_))[tid];
    val.x -= as * cw.x; val.y -= as * cw.y; val.z -= as * cw.z; val.w -= as * cw.w;
    float ss = val.x * val.x + val.y * val.y + val.z * val.z + val.w * val.w;
#pragma unroll
    for (int o = 16; o; o >>= 1) ss += __shfl_xor_sync(0xffffffff, ss, o);
    __shared__ float wss[4];
    if ((tid & 31) == 0) wss[tid >> 5] = ss;
    __syncthreads();
    float tot = wss[0] + wss[1] + wss[2] + wss[3];
    float sc  = 1.f / fmaxf(sqrtf(tot), 1e-12f);
    val.x *= sc; val.y *= sc; val.z *= sc; val.w *= sc;
    ((float4*)v)[tid] = val;
    if (tid == 0) atomicAdd(&g_gss[t], tot * sc * sc);
}

// ---------------- pass 4: global normalize + sum over t ----------------
__global__ __launch_bounds__(256) void finalize_kernel(float* __restrict__ out) {
    __shared__ float gsc[T_];
    const int tid = threadIdx.x;
    if (tid < T_) gsc[tid] = 1.f / fmaxf(sqrtf(g_gss[tid]), 1e-12f);
    __syncthreads();
    const int i = blockIdx.x * 256 + tid;
    float s = 0.f;
    for (int t = 0; t < T_; t++)
        s += g_vlad[(size_t)t * KD_ + i] * gsc[t];
    out[i] = s;
}

// ---------------- launch ----------------
extern "C" void kernel_launch(void* const* d_in, const int* in_sizes, int n_in,
                              void* d_out, int out_size) {
    const float* x1     = (const float*)d_in[0];   // [30,512,28,28]
    const float* cent   = (const float*)d_in[1];   // [64,512]
    const float* conv_w = (const float*)d_in[2];   // [64,512]
    const float* conv_b = (const float*)d_in[3];   // [64]
    float* out = (float*)d_out;                    // [1, 32768]

    prep_kernel<<<(T_ * K_ * C_ + 255) / 256, 256>>>(conv_w);
    {
        dim3 g((N_ + 63) / 64, T_);
        assign_kernel<<<g, 128>>>(x1, conv_b);
    }
    {
        dim3 g(C_ / 64, 3, T_);
        vlad_kernel<<<g, 128>>>(x1);
    }
    {
        dim3 g(K_, T_);
        intranorm_kernel<<<g, 128>>>(cent);
    }
    finalize_kernel<<<KD_ / 256, 256>>>(out);
}

// round 6
// speedup vs baseline: 1.3434x; 1.0170x over previous
#include <cuda_runtime.h>
#include <math.h>

#define T_ 30
#define C_ 512
#define N_ 784
#define K_ 64
#define KD_ (K_ * C_)   // 32768

// ---------------- device scratch (no allocs allowed) ----------------
__device__ float g_wT[C_ * K_];            // conv_w transposed: [c][k]
__device__ float g_aT[T_ * N_ * K_];       // a' = softmax * invn, layout [t][n][k]
__device__ float g_asum[T_ * K_];          // sum_n a[t,k,n]
__device__ float g_vladA[T_ * K_ * C_];    // partial s0, later the normalized vlad
__device__ float g_vladB[T_ * K_ * C_];    // partial s1
__device__ float g_gss[T_];                // global sumsq per t

// ---------------- packed f32x2 helpers ----------------
typedef unsigned long long u64;
__device__ __forceinline__ u64 pk2(float lo, float hi) {
    u64 r;
    asm("mov.b64 %0, {%1, %2};" : "=l"(r) : "f"(lo), "f"(hi));
    return r;
}
__device__ __forceinline__ void upk2(u64 v, float& lo, float& hi) {
    asm("mov.b64 {%0, %1}, %2;" : "=f"(lo), "=f"(hi) : "l"(v));
}
__device__ __forceinline__ void fma2(u64& d, u64 a, u64 b) {
    asm("fma.rn.f32x2 %0, %1, %2, %0;" : "+l"(d) : "l"(a), "l"(b));
}

// ---------------- pass 0: transpose W, zero small accumulators ----------------
__global__ void prep_kernel(const float* __restrict__ w) {
    int i = blockIdx.x * 256 + threadIdx.x;
    if (i < C_ * K_) {
        int k = i / C_, c = i % C_;
        g_wT[c * K_ + k] = w[i];
    }
    if (i < T_ * K_) g_asum[i] = 0.f;
    if (i < T_)      g_gss[i]  = 0.f;
}

// ---------------- pass 1: invnorm + logits GEMM + softmax -> aT', asum ----------------
// grid: (13, T), block 128.  Tile: K=64 x N=64, per-thread 8k x 4n via f32x2.
__global__ __launch_bounds__(128) void assign_kernel(
    const float* __restrict__ x, const float* __restrict__ bias)
{
    const int t   = blockIdx.y;
    const int n0  = blockIdx.x * 64;
    const int tid = threadIdx.x;
    const int tyk = tid >> 4;          // 0..7  -> k0 = tyk*8
    const int txn = tid & 15;          // 0..15 -> nl = txn*4
    const int k0  = tyk * 8;
    const int nl  = txn * 4;

    __shared__ float Ws[32 * 64];      // [ci][k]
    __shared__ float Xs[32 * 64];      // [ci][nj]
    __shared__ float Ls[64 * 64];      // logits/exp [k][n]
    __shared__ float red[2 * 64];
    __shared__ float invn_s[64];
    __shared__ float rinvs[64];
    __shared__ float bsm[64];

    if (tid < 64) bsm[tid] = bias[tid];

    u64 acc[4][4];
#pragma unroll
    for (int p = 0; p < 4; p++)
#pragma unroll
        for (int j = 0; j < 4; j++) acc[p][j] = 0ull;

    const int col  = tid & 63;
    const int half = tid >> 6;
    float ss = 0.f;

    const float* xt = x + (size_t)t * C_ * N_;

    for (int cc = 0; cc < 16; cc++) {
#pragma unroll
        for (int j = 0; j < 4; j++) {
            int idx4 = tid + j * 128;
            ((float4*)Ws)[idx4] = ((const float4*)(g_wT + cc * 2048))[idx4];
        }
#pragma unroll
        for (int j = 0; j < 4; j++) {
            int idx4 = tid + j * 128;
            int ci = idx4 >> 4, c4 = idx4 & 15;
            int n  = n0 + c4 * 4;
            float4 v = make_float4(0.f, 0.f, 0.f, 0.f);
            if (n < N_) v = *(const float4*)&xt[(size_t)(cc * 32 + ci) * N_ + n];
            ((float4*)Xs)[idx4] = v;
        }
        __syncthreads();

        // per-column sumsq (2 threads per column, 16 ci each)
#pragma unroll
        for (int ci = half * 16; ci < half * 16 + 16; ci++) {
            float v = Xs[ci * 64 + col];
            ss += v * v;
        }

#pragma unroll
        for (int ci = 0; ci < 32; ci++) {
            float4 wa = *(const float4*)&Ws[ci * 64 + k0];
            float4 wb = *(const float4*)&Ws[ci * 64 + k0 + 4];
            float4 xv = *(const float4*)&Xs[ci * 64 + nl];
            u64 wp0 = pk2(wa.x, wa.y), wp1 = pk2(wa.z, wa.w);
            u64 wp2 = pk2(wb.x, wb.y), wp3 = pk2(wb.z, wb.w);
            u64 xd0 = pk2(xv.x, xv.x), xd1 = pk2(xv.y, xv.y);
            u64 xd2 = pk2(xv.z, xv.z), xd3 = pk2(xv.w, xv.w);
            fma2(acc[0][0], wp0, xd0); fma2(acc[0][1], wp0, xd1);
            fma2(acc[0][2], wp0, xd2); fma2(acc[0][3], wp0, xd3);
            fma2(acc[1][0], wp1, xd0); fma2(acc[1][1], wp1, xd1);
            fma2(acc[1][2], wp1, xd2); fma2(acc[1][3], wp1, xd3);
            fma2(acc[2][0], wp2, xd0); fma2(acc[2][1], wp2, xd1);
            fma2(acc[2][2], wp2, xd2); fma2(acc[2][3], wp2, xd3);
            fma2(acc[3][0], wp3, xd0); fma2(acc[3][1], wp3, xd1);
            fma2(acc[3][2], wp3, xd2); fma2(acc[3][3], wp3, xd3);
        }
        __syncthreads();
    }

    // reduce sumsq halves -> invn
    red[half * 64 + col] = ss;
    __syncthreads();
    if (tid < 64) {
        float sst = red[tid] + red[64 + tid];
        invn_s[tid] = 1.f / fmaxf(sqrtf(sst), 1e-12f);
    }
    __syncthreads();

    // unpack accumulators -> logits in Ls
    // acc[p][j]: lane-lo = (k0+2p, nl+j), lane-hi = (k0+2p+1, nl+j)
#pragma unroll
    for (int p = 0; p < 4; p++) {
        int r0 = k0 + 2 * p, r1 = r0 + 1;
        float b0 = bsm[r0], b1 = bsm[r1];
#pragma unroll
        for (int j = 0; j < 4; j++) {
            int cA = nl + j;
            float iA = invn_s[cA];
            float lo, hi;
            upk2(acc[p][j], lo, hi);
            Ls[r0 * 64 + cA] = lo * iA + b0;
            Ls[r1 * 64 + cA] = hi * iA + b1;
        }
    }
    __syncthreads();

    // softmax over k per column: 2 threads per column, 32 rows each
    float m = -1e30f;
#pragma unroll
    for (int kk = 0; kk < 32; kk++) m = fmaxf(m, Ls[(half * 32 + kk) * 64 + col]);
    red[half * 64 + col] = m;
    __syncthreads();
    m = fmaxf(red[col], red[64 + col]);
    __syncthreads();
    float s = 0.f;
#pragma unroll
    for (int kk = 0; kk < 32; kk++) {
        float e = __expf(Ls[(half * 32 + kk) * 64 + col] - m);
        Ls[(half * 32 + kk) * 64 + col] = e;
        s += e;
    }
    red[half * 64 + col] = s;
    __syncthreads();
    const int  n     = n0 + col;
    const bool valid = (n < N_);
    float S    = red[col] + red[64 + col];
    float rinv = valid ? (1.f / S) : 0.f;
    if (half == 0) rinvs[col] = rinv;
    __syncthreads();

    // write aT' = a * invn  (layout [t][n][k]) — vectorized float4 stores
    if (valid) {
        float  sc  = rinv * invn_s[col];
        float4* dst = (float4*)&g_aT[((size_t)t * N_ + n) * K_ + half * 32];
#pragma unroll
        for (int q = 0; q < 8; q++) {
            int kb = half * 32 + q * 4;
            float4 v;
            v.x = Ls[(kb + 0) * 64 + col] * sc;
            v.y = Ls[(kb + 1) * 64 + col] * sc;
            v.z = Ls[(kb + 2) * 64 + col] * sc;
            v.w = Ls[(kb + 3) * 64 + col] * sc;
            dst[q] = v;
        }
    }

    // partial asum per k (staggered columns -> conflict-free)
    if (tid < 64) {
        float as = 0.f;
#pragma unroll 8
        for (int c2 = 0; c2 < 64; c2++) {
            int cix = (c2 + tid) & 63;
            as += Ls[tid * 64 + cix] * rinvs[cix];
        }
        atomicAdd(&g_asum[t * K_ + tid], as);
    }
}

// ---------------- pass 2: VLAD GEMM (split-2 into disjoint slabs, NO atomics) ----------------
// grid: (8, 2, T), block 128.  Tile: K=64 x C=64, per-thread 8k x 4c via f32x2.
__global__ __launch_bounds__(128) void vlad_kernel(const float* __restrict__ x)
{
    const int t   = blockIdx.z;
    const int c0  = blockIdx.x * 64;
    const int s   = blockIdx.y;
    const int tid = threadIdx.x;
    const int tyk = tid >> 4;
    const int txc = tid & 15;
    const int k0  = tyk * 8;
    const int cl  = txc * 4;

    __shared__ float As[32 * 64];    // [nn][k]
    __shared__ float XsT[32 * 68];   // [nn][ci] padded

    u64 acc[4][4];
#pragma unroll
    for (int p = 0; p < 4; p++)
#pragma unroll
        for (int j = 0; j < 4; j++) acc[p][j] = 0ull;

    const float* xt  = x + (size_t)t * C_ * N_;
    const float* aTt = g_aT + (size_t)t * N_ * K_;

    const int cb = (s == 0) ? 0  : 13;
    const int ce = (s == 0) ? 13 : 25;

    for (int nc = cb; nc < ce; nc++) {
        const int n0 = nc * 32;
#pragma unroll
        for (int j = 0; j < 4; j++) {
            int idx4 = tid + j * 128;
            int nn = idx4 >> 4, k4 = idx4 & 15;
            float4 v = make_float4(0.f, 0.f, 0.f, 0.f);
            if (n0 + nn < N_) v = *(const float4*)&aTt[(size_t)(n0 + nn) * K_ + k4 * 4];
            ((float4*)As)[idx4] = v;
        }
        // full 64-wide c tile: e in [0, 2048), ci in [0,64)
#pragma unroll
        for (int j = 0; j < 16; j++) {
            int e  = tid + j * 128;
            int ci = e >> 5, nn = e & 31;
            float v = (n0 + nn < N_) ? xt[(size_t)(c0 + ci) * N_ + n0 + nn] : 0.f;
            XsT[nn * 68 + ci] = v;
        }
        __syncthreads();
#pragma unroll
        for (int nn = 0; nn < 32; nn++) {
            float4 aa = *(const float4*)&As[nn * 64 + k0];
            float4 ab = *(const float4*)&As[nn * 64 + k0 + 4];
            float4 xv = *(const float4*)&XsT[nn * 68 + cl];
            u64 ap0 = pk2(aa.x, aa.y), ap1 = pk2(aa.z, aa.w);
            u64 ap2 = pk2(ab.x, ab.y), ap3 = pk2(ab.z, ab.w);
            u64 xd0 = pk2(xv.x, xv.x), xd1 = pk2(xv.y, xv.y);
            u64 xd2 = pk2(xv.z, xv.z), xd3 = pk2(xv.w, xv.w);
            fma2(acc[0][0], ap0, xd0); fma2(acc[0][1], ap0, xd1);
            fma2(acc[0][2], ap0, xd2); fma2(acc[0][3], ap0, xd3);
            fma2(acc[1][0], ap1, xd0); fma2(acc[1][1], ap1, xd1);
            fma2(acc[1][2], ap1, xd2); fma2(acc[1][3], ap1, xd3);
            fma2(acc[2][0], ap2, xd0); fma2(acc[2][1], ap2, xd1);
            fma2(acc[2][2], ap2, xd2); fma2(acc[2][3], ap2, xd3);
            fma2(acc[3][0], ap3, xd0); fma2(acc[3][1], ap3, xd1);
            fma2(acc[3][2], ap3, xd2); fma2(acc[3][3], ap3, xd3);
        }
        __syncthreads();
    }

    // epilogue: plain float4 stores into this split's slab
    // acc[p][j]: lane-lo = (k0+2p, cl+j), lane-hi = (k0+2p+1, cl+j)
    float* slab = (s == 0) ? g_vladA : g_vladB;
#pragma unroll
    for (int p = 0; p < 4; p++) {
        int r0 = k0 + 2 * p, r1 = r0 + 1;
        float lo0, hi0, lo1, hi1, lo2, hi2, lo3, hi3;
        upk2(acc[p][0], lo0, hi0);
        upk2(acc[p][1], lo1, hi1);
        upk2(acc[p][2], lo2, hi2);
        upk2(acc[p][3], lo3, hi3);
        float4 v0 = make_float4(lo0, lo1, lo2, lo3);
        float4 v1 = make_float4(hi0, hi1, hi2, hi3);
        *(float4*)&slab[((size_t)t * K_ + r0) * C_ + c0 + cl] = v0;
        *(float4*)&slab[((size_t)t * K_ + r1) * C_ + c0 + cl] = v1;
    }
}

// ---------------- pass 3: sum partials + (-asum*cent) + intra-norm (warp per row) ----------------
// grid: T*K/8 = 240, block 256 (8 warps, one (t,k) row each)
__global__ __launch_bounds__(256) void intranorm_kernel(const float* __restrict__ cent) {
    const int warp = threadIdx.x >> 5;
    const int lane = threadIdx.x & 31;
    const int row  = blockIdx.x * 8 + warp;       // row in [0, T*K)
    const int t = row >> 6, k = row & 63;

    const size_t base4 = (size_t)row * (C_ / 4);  // float4 index base
    const float4* A = (const float4*)g_vladA;
    const float4* B = (const float4*)g_vladB;
    const float4* CW = (const float4*)cent;
    const float as = g_asum[t * K_ + k];

    float4 val[4];
    float ss = 0.f;
#pragma unroll
    for (int q = 0; q < 4; q++) {
        int idx = q * 32 + lane;
        float4 a = A[base4 + idx];
        float4 b = B[base4 + idx];
        float4 cw = CW[(size_t)k * (C_ / 4) + idx];
        float4 v;
        v.x = a.x + b.x - as * cw.x;
        v.y = a.y + b.y - as * cw.y;
        v.z = a.z + b.z - as * cw.z;
        v.w = a.w + b.w - as * cw.w;
        val[q] = v;
        ss += v.x * v.x + v.y * v.y + v.z * v.z + v.w * v.w;
    }
#pragma unroll
    for (int o = 16; o; o >>= 1) ss += __shfl_xor_sync(0xffffffff, ss, o);
    float sc = 1.f / fmaxf(sqrtf(ss), 1e-12f);
    float4* Aout = (float4*)g_vladA;
#pragma unroll
    for (int q = 0; q < 4; q++) {
        int idx = q * 32 + lane;
        float4 v = val[q];
        v.x *= sc; v.y *= sc; v.z *= sc; v.w *= sc;
        Aout[base4 + idx] = v;
    }
    if (lane == 0) atomicAdd(&g_gss[t], ss * sc * sc);
}

// ---------------- pass 4: global normalize + sum over t ----------------
__global__ __launch_bounds__(256) void finalize_kernel(float* __restrict__ out) {
    __shared__ float gsc[T_];
    const int tid = threadIdx.x;
    if (tid < T_) gsc[tid] = 1.f / fmaxf(sqrtf(g_gss[tid]), 1e-12f);
    __syncthreads();
    const int i = blockIdx.x * 256 + tid;
    float s = 0.f;
    for (int t = 0; t < T_; t++)
        s += g_vladA[(size_t)t * KD_ + i] * gsc[t];
    out[i] = s;
}

// ---------------- launch ----------------
extern "C" void kernel_launch(void* const* d_in, const int* in_sizes, int n_in,
                              void* d_out, int out_size) {
    const float* x1     = (const float*)d_in[0];   // [30,512,28,28]
    const float* cent   = (const float*)d_in[1];   // [64,512]
    const float* conv_w = (const float*)d_in[2];   // [64,512]
    const float* conv_b = (const float*)d_in[3];   // [64]
    float* out = (float*)d_out;                    // [1, 32768]

    prep_kernel<<<128, 256>>>(conv_w);
    {
        dim3 g((N_ + 63) / 64, T_);
        assign_kernel<<<g, 128>>>(x1, conv_b);
    }
    {
        dim3 g(C_ / 64, 2, T_);
        vlad_kernel<<<g, 128>>>(x1);
    }
    intranorm_kernel<<<(T_ * K_) / 8, 256>>>(cent);
    finalize_kernel<<<KD_ / 256, 256>>>(out);
}

// round 7
// speedup vs baseline: 1.4002x; 1.0423x over previous
#include <cuda_runtime.h>
#include <math.h>

#define T_ 30
#define C_ 512
#define N_ 784
#define K_ 64
#define KD_ (K_ * C_)   // 32768

// ---------------- device scratch (no allocs allowed) ----------------
__device__ float g_wT[C_ * K_];            // conv_w transposed: [c][k]
__device__ float g_aT[T_ * N_ * K_];       // a' = softmax * invn, layout [t][n][k]
__device__ float g_asum[T_ * K_];          // sum_n a[t,k,n]
__device__ float g_vladA[T_ * K_ * C_];    // partial s0, later the normalized vlad
__device__ float g_vladB[T_ * K_ * C_];    // partial s1
__device__ float g_gss[T_];                // global sumsq per t

// ---------------- packed f32x2 helpers ----------------
typedef unsigned long long u64;
__device__ __forceinline__ u64 pk2(float lo, float hi) {
    u64 r;
    asm("mov.b64 %0, {%1, %2};" : "=l"(r) : "f"(lo), "f"(hi));
    return r;
}
__device__ __forceinline__ void upk2(u64 v, float& lo, float& hi) {
    asm("mov.b64 {%0, %1}, %2;" : "=f"(lo), "=f"(hi) : "l"(v));
}
__device__ __forceinline__ void fma2(u64& d, u64 a, u64 b) {
    asm("fma.rn.f32x2 %0, %1, %2, %0;" : "+l"(d) : "l"(a), "l"(b));
}

// ---------------- pass 0: transpose W, zero small accumulators ----------------
__global__ void prep_kernel(const float* __restrict__ w) {
    int i = blockIdx.x * 256 + threadIdx.x;
    if (i < C_ * K_) {
        int k = i / C_, c = i % C_;
        g_wT[c * K_ + k] = w[i];
    }
    if (i < T_ * K_) g_asum[i] = 0.f;
    if (i < T_)      g_gss[i]  = 0.f;
}

// ---------------- pass 1: invnorm + logits GEMM + softmax -> aT', asum ----------------
// grid: (13, T), block 128.  Tile: K=64 x N=64, double-buffered k-chunks.
__global__ __launch_bounds__(128) void assign_kernel(
    const float* __restrict__ x, const float* __restrict__ bias)
{
    const int t   = blockIdx.y;
    const int n0  = blockIdx.x * 64;
    const int tid = threadIdx.x;
    const int tyk = tid >> 4;          // 0..7  -> k0 = tyk*8
    const int txn = tid & 15;          // 0..15 -> nl = txn*4
    const int k0  = tyk * 8;
    const int nl  = txn * 4;

    __shared__ float Ws[2][2048];      // [buf][ci][k]
    __shared__ float Xs[2][2048];      // [buf][ci][nj]
    __shared__ float Ls[64 * 64];      // logits/exp [k][n]
    __shared__ float red[2 * 64];
    __shared__ float invn_s[64];
    __shared__ float rinvs[64];
    __shared__ float bsm[64];

    if (tid < 64) bsm[tid] = bias[tid];

    u64 acc[4][4];
#pragma unroll
    for (int p = 0; p < 4; p++)
#pragma unroll
        for (int j = 0; j < 4; j++) acc[p][j] = 0ull;

    const int col  = tid & 63;
    const int half = tid >> 6;
    float ss = 0.f;

    const float* xt = x + (size_t)t * C_ * N_;

    // prologue: fill buffer 0 with chunk cc=0
#pragma unroll
    for (int j = 0; j < 4; j++) {
        int idx4 = tid + j * 128;
        ((float4*)Ws[0])[idx4] = ((const float4*)g_wT)[idx4];
        int ci = idx4 >> 4, c4 = idx4 & 15;
        int n  = n0 + c4 * 4;
        float4 v = make_float4(0.f, 0.f, 0.f, 0.f);
        if (n < N_) v = *(const float4*)&xt[(size_t)ci * N_ + n];
        ((float4*)Xs[0])[idx4] = v;
    }
    __syncthreads();

    for (int cc = 0; cc < 16; cc++) {
        const int p = cc & 1;
        float4 wpre[4], xpre[4];
        if (cc < 15) {
#pragma unroll
            for (int j = 0; j < 4; j++) {
                int idx4 = tid + j * 128;
                wpre[j] = ((const float4*)(g_wT + (cc + 1) * 2048))[idx4];
                int ci = idx4 >> 4, c4 = idx4 & 15;
                int n  = n0 + c4 * 4;
                xpre[j] = make_float4(0.f, 0.f, 0.f, 0.f);
                if (n < N_) xpre[j] = *(const float4*)&xt[(size_t)((cc + 1) * 32 + ci) * N_ + n];
            }
        }

        const float* Wp = Ws[p];
        const float* Xp = Xs[p];

        // per-column sumsq (2 threads per column, 16 ci each)
#pragma unroll
        for (int q = 0; q < 16; q++) {
            float v = Xp[(half * 16 + q) * 64 + col];
            ss += v * v;
        }

#pragma unroll
        for (int ci = 0; ci < 32; ci++) {
            float4 wa = *(const float4*)&Wp[ci * 64 + k0];
            float4 wb = *(const float4*)&Wp[ci * 64 + k0 + 4];
            float4 xv = *(const float4*)&Xp[ci * 64 + nl];
            u64 wp0 = pk2(wa.x, wa.y), wp1 = pk2(wa.z, wa.w);
            u64 wp2 = pk2(wb.x, wb.y), wp3 = pk2(wb.z, wb.w);
            u64 xd0 = pk2(xv.x, xv.x), xd1 = pk2(xv.y, xv.y);
            u64 xd2 = pk2(xv.z, xv.z), xd3 = pk2(xv.w, xv.w);
            fma2(acc[0][0], wp0, xd0); fma2(acc[0][1], wp0, xd1);
            fma2(acc[0][2], wp0, xd2); fma2(acc[0][3], wp0, xd3);
            fma2(acc[1][0], wp1, xd0); fma2(acc[1][1], wp1, xd1);
            fma2(acc[1][2], wp1, xd2); fma2(acc[1][3], wp1, xd3);
            fma2(acc[2][0], wp2, xd0); fma2(acc[2][1], wp2, xd1);
            fma2(acc[2][2], wp2, xd2); fma2(acc[2][3], wp2, xd3);
            fma2(acc[3][0], wp3, xd0); fma2(acc[3][1], wp3, xd1);
            fma2(acc[3][2], wp3, xd2); fma2(acc[3][3], wp3, xd3);
        }

        if (cc < 15) {
#pragma unroll
            for (int j = 0; j < 4; j++) {
                int idx4 = tid + j * 128;
                ((float4*)Ws[p ^ 1])[idx4] = wpre[j];
                ((float4*)Xs[p ^ 1])[idx4] = xpre[j];
            }
            __syncthreads();
        }
    }

    // reduce sumsq halves -> invn
    red[half * 64 + col] = ss;
    __syncthreads();
    if (tid < 64) {
        float sst = red[tid] + red[64 + tid];
        invn_s[tid] = 1.f / fmaxf(sqrtf(sst), 1e-12f);
    }
    __syncthreads();

    // unpack accumulators -> logits in Ls
    // acc[p][j]: lane-lo = (k0+2p, nl+j), lane-hi = (k0+2p+1, nl+j)
#pragma unroll
    for (int p = 0; p < 4; p++) {
        int r0 = k0 + 2 * p, r1 = r0 + 1;
        float b0 = bsm[r0], b1 = bsm[r1];
#pragma unroll
        for (int j = 0; j < 4; j++) {
            int cA = nl + j;
            float iA = invn_s[cA];
            float lo, hi;
            upk2(acc[p][j], lo, hi);
            Ls[r0 * 64 + cA] = lo * iA + b0;
            Ls[r1 * 64 + cA] = hi * iA + b1;
        }
    }
    __syncthreads();

    // softmax over k per column: 2 threads per column, 32 rows each
    float m = -1e30f;
#pragma unroll
    for (int kk = 0; kk < 32; kk++) m = fmaxf(m, Ls[(half * 32 + kk) * 64 + col]);
    red[half * 64 + col] = m;
    __syncthreads();
    m = fmaxf(red[col], red[64 + col]);
    __syncthreads();
    float s = 0.f;
#pragma unroll
    for (int kk = 0; kk < 32; kk++) {
        float e = __expf(Ls[(half * 32 + kk) * 64 + col] - m);
        Ls[(half * 32 + kk) * 64 + col] = e;
        s += e;
    }
    red[half * 64 + col] = s;
    __syncthreads();
    const int  n     = n0 + col;
    const bool valid = (n < N_);
    float S    = red[col] + red[64 + col];
    float rinv = valid ? (1.f / S) : 0.f;
    if (half == 0) rinvs[col] = rinv;
    __syncthreads();

    // write aT' = a * invn  (layout [t][n][k]) — float4 stores
    if (valid) {
        float  sc  = rinv * invn_s[col];
        float4* dst = (float4*)&g_aT[((size_t)t * N_ + n) * K_ + half * 32];
#pragma unroll
        for (int q = 0; q < 8; q++) {
            int kb = half * 32 + q * 4;
            float4 v;
            v.x = Ls[(kb + 0) * 64 + col] * sc;
            v.y = Ls[(kb + 1) * 64 + col] * sc;
            v.z = Ls[(kb + 2) * 64 + col] * sc;
            v.w = Ls[(kb + 3) * 64 + col] * sc;
            dst[q] = v;
        }
    }

    // partial asum per k (staggered columns -> conflict-free)
    if (tid < 64) {
        float as = 0.f;
#pragma unroll 8
        for (int c2 = 0; c2 < 64; c2++) {
            int cix = (c2 + tid) & 63;
            as += Ls[tid * 64 + cix] * rinvs[cix];
        }
        atomicAdd(&g_asum[t * K_ + tid], as);
    }
}

// ---------------- pass 2: VLAD GEMM (split-2 disjoint slabs, double-buffered) ----------------
// grid: (8, 2, T), block 128.  Tile: K=64 x C=64.
__global__ __launch_bounds__(128) void vlad_kernel(const float* __restrict__ x)
{
    const int t   = blockIdx.z;
    const int c0  = blockIdx.x * 64;
    const int s   = blockIdx.y;
    const int tid = threadIdx.x;
    const int tyk = tid >> 4;
    const int txc = tid & 15;
    const int k0  = tyk * 8;
    const int cl  = txc * 4;

    __shared__ float As[2][2048];      // [buf][nn][k]
    __shared__ float XsT[2][32 * 68];  // [buf][nn][ci] padded

    u64 acc[4][4];
#pragma unroll
    for (int p = 0; p < 4; p++)
#pragma unroll
        for (int j = 0; j < 4; j++) acc[p][j] = 0ull;

    const float* xt  = x + (size_t)t * C_ * N_;
    const float* aTt = g_aT + (size_t)t * N_ * K_;

    const int cb = (s == 0) ? 0  : 13;
    const int NC = (s == 0) ? 13 : 12;   // chunks [cb, cb+NC)

    // prologue: chunk cb -> buffer 0
    {
        const int n0 = cb * 32;
#pragma unroll
        for (int j = 0; j < 4; j++) {
            int idx4 = tid + j * 128;
            int nn = idx4 >> 4, k4 = idx4 & 15;
            float4 v = make_float4(0.f, 0.f, 0.f, 0.f);
            if (n0 + nn < N_) v = *(const float4*)&aTt[(size_t)(n0 + nn) * K_ + k4 * 4];
            ((float4*)As[0])[idx4] = v;
        }
#pragma unroll
        for (int j = 0; j < 16; j++) {
            int e  = tid + j * 128;
            int ci = e >> 5, nn = e & 31;
            float v = (n0 + nn < N_) ? xt[(size_t)(c0 + ci) * N_ + n0 + nn] : 0.f;
            XsT[0][nn * 68 + ci] = v;
        }
    }
    __syncthreads();

    for (int i = 0; i < NC; i++) {
        const int p = i & 1;
        float4 apre[4];
        float  xpre[16];
        if (i + 1 < NC) {
            const int n0 = (cb + i + 1) * 32;
#pragma unroll
            for (int j = 0; j < 4; j++) {
                int idx4 = tid + j * 128;
                int nn = idx4 >> 4, k4 = idx4 & 15;
                apre[j] = make_float4(0.f, 0.f, 0.f, 0.f);
                if (n0 + nn < N_) apre[j] = *(const float4*)&aTt[(size_t)(n0 + nn) * K_ + k4 * 4];
            }
#pragma unroll
            for (int j = 0; j < 16; j++) {
                int e  = tid + j * 128;
                int ci = e >> 5, nn = e & 31;
                xpre[j] = (n0 + nn < N_) ? xt[(size_t)(c0 + ci) * N_ + n0 + nn] : 0.f;
            }
        }

        const float* Ap = As[p];
        const float* Xp = XsT[p];
#pragma unroll
        for (int nn = 0; nn < 32; nn++) {
            float4 aa = *(const float4*)&Ap[nn * 64 + k0];
            float4 ab = *(const float4*)&Ap[nn * 64 + k0 + 4];
            float4 xv = *(const float4*)&Xp[nn * 68 + cl];
            u64 ap0 = pk2(aa.x, aa.y), ap1 = pk2(aa.z, aa.w);
            u64 ap2 = pk2(ab.x, ab.y), ap3 = pk2(ab.z, ab.w);
            u64 xd0 = pk2(xv.x, xv.x), xd1 = pk2(xv.y, xv.y);
            u64 xd2 = pk2(xv.z, xv.z), xd3 = pk2(xv.w, xv.w);
            fma2(acc[0][0], ap0, xd0); fma2(acc[0][1], ap0, xd1);
            fma2(acc[0][2], ap0, xd2); fma2(acc[0][3], ap0, xd3);
            fma2(acc[1][0], ap1, xd0); fma2(acc[1][1], ap1, xd1);
            fma2(acc[1][2], ap1, xd2); fma2(acc[1][3], ap1, xd3);
            fma2(acc[2][0], ap2, xd0); fma2(acc[2][1], ap2, xd1);
            fma2(acc[2][2], ap2, xd2); fma2(acc[2][3], ap2, xd3);
            fma2(acc[3][0], ap3, xd0); fma2(acc[3][1], ap3, xd1);
            fma2(acc[3][2], ap3, xd2); fma2(acc[3][3], ap3, xd3);
        }

        if (i + 1 < NC) {
#pragma unroll
            for (int j = 0; j < 4; j++)
                ((float4*)As[p ^ 1])[tid + j * 128] = apre[j];
#pragma unroll
            for (int j = 0; j < 16; j++) {
                int e  = tid + j * 128;
                int ci = e >> 5, nn = e & 31;
                XsT[p ^ 1][nn * 68 + ci] = xpre[j];
            }
            __syncthreads();
        }
    }

    // epilogue: plain float4 stores into this split's slab
    float* slab = (s == 0) ? g_vladA : g_vladB;
#pragma unroll
    for (int p = 0; p < 4; p++) {
        int r0 = k0 + 2 * p, r1 = r0 + 1;
        float lo0, hi0, lo1, hi1, lo2, hi2, lo3, hi3;
        upk2(acc[p][0], lo0, hi0);
        upk2(acc[p][1], lo1, hi1);
        upk2(acc[p][2], lo2, hi2);
        upk2(acc[p][3], lo3, hi3);
        float4 v0 = make_float4(lo0, lo1, lo2, lo3);
        float4 v1 = make_float4(hi0, hi1, hi2, hi3);
        *(float4*)&slab[((size_t)t * K_ + r0) * C_ + c0 + cl] = v0;
        *(float4*)&slab[((size_t)t * K_ + r1) * C_ + c0 + cl] = v1;
    }
}

// ---------------- pass 3: sum partials + (-asum*cent) + intra-norm (warp per row) ----------------
// grid: T*K/4 = 480, block 128 (4 warps, one (t,k) row each)
__global__ __launch_bounds__(128) void intranorm_kernel(const float* __restrict__ cent) {
    const int warp = threadIdx.x >> 5;
    const int lane = threadIdx.x & 31;
    const int row  = blockIdx.x * 4 + warp;       // row in [0, T*K)
    const int t = row >> 6, k = row & 63;

    const size_t base4 = (size_t)row * (C_ / 4);  // float4 index base
    const float4* A = (const float4*)g_vladA;
    const float4* B = (const float4*)g_vladB;
    const float4* CW = (const float4*)cent;
    const float as = g_asum[t * K_ + k];

    float4 val[4];
    float ss = 0.f;
#pragma unroll
    for (int q = 0; q < 4; q++) {
        int idx = q * 32 + lane;
        float4 a = A[base4 + idx];
        float4 b = B[base4 + idx];
        float4 cw = CW[(size_t)k * (C_ / 4) + idx];
        float4 v;
        v.x = a.x + b.x - as * cw.x;
        v.y = a.y + b.y - as * cw.y;
        v.z = a.z + b.z - as * cw.z;
        v.w = a.w + b.w - as * cw.w;
        val[q] = v;
        ss += v.x * v.x + v.y * v.y + v.z * v.z + v.w * v.w;
    }
#pragma unroll
    for (int o = 16; o; o >>= 1) ss += __shfl_xor_sync(0xffffffff, ss, o);
    float sc = 1.f / fmaxf(sqrtf(ss), 1e-12f);
    float4* Aout = (float4*)g_vladA;
#pragma unroll
    for (int q = 0; q < 4; q++) {
        int idx = q * 32 + lane;
        float4 v = val[q];
        v.x *= sc; v.y *= sc; v.z *= sc; v.w *= sc;
        Aout[base4 + idx] = v;
    }
    if (lane == 0) atomicAdd(&g_gss[t], ss * sc * sc);
}

// ---------------- pass 4: global normalize + sum over t ----------------
__global__ __launch_bounds__(256) void finalize_kernel(float* __restrict__ out) {
    __shared__ float gsc[T_];
    const int tid = threadIdx.x;
    if (tid < T_) gsc[tid] = 1.f / fmaxf(sqrtf(g_gss[tid]), 1e-12f);
    __syncthreads();
    const int i = blockIdx.x * 256 + tid;
    float s = 0.f;
    for (int t = 0; t < T_; t++)
        s += g_vladA[(size_t)t * KD_ + i] * gsc[t];
    out[i] = s;
}

// ---------------- launch ----------------
extern "C" void kernel_launch(void* const* d_in, const int* in_sizes, int n_in,
                              void* d_out, int out_size) {
    const float* x1     = (const float*)d_in[0];   // [30,512,28,28]
    const float* cent   = (const float*)d_in[1];   // [64,512]
    const float* conv_w = (const float*)d_in[2];   // [64,512]
    const float* conv_b = (const float*)d_in[3];   // [64]
    float* out = (float*)d_out;                    // [1, 32768]

    prep_kernel<<<128, 256>>>(conv_w);
    {
        dim3 g((N_ + 63) / 64, T_);
        assign_kernel<<<g, 128>>>(x1, conv_b);
    }
    {
        dim3 g(C_ / 64, 2, T_);
        vlad_kernel<<<g, 128>>>(x1);
    }
    intranorm_kernel<<<(T_ * K_) / 4, 128>>>(cent);
    finalize_kernel<<<KD_ / 256, 256>>>(out);
}